// round 6
// baseline (speedup 1.0000x reference)
#include <cuda_runtime.h>

// Fixed problem shape (SGConv_52613349376206): B=4, N=16384, D=128, E=1048576
#define BB 4
#define NN 16384
#define DD 128
#define BN (BB * NN)   // 65536 rows

// Scratch (static __device__ arrays: allocation-free per harness rules)
__device__ float              g_deg[BN];                 // 256 KB  sum |val| per dst
__device__ int                g_cnt[BN];                 // 256 KB  edge count per dst
__device__ int                g_rowptr[BN + 1];          // CSR row pointers
__device__ int                g_cur[BN];                 // scatter cursors
__device__ unsigned long long g_sorted[1 << 20];         // 8 MB   packed (val,src) per edge
__device__ float              g_y[(size_t)BN * DD];      // 32 MB  y = (x@W)*norm[src]

// packed fp32x2 FMA (Blackwell): acc = a*b + acc on both 32-bit halves
#define FMA2(acc, a, b) \
    asm("fma.rn.f32x2 %0, %1, %2, %0;" : "+l"(acc) : "l"(a), "l"(b))

// ---------------------------------------------------------------------------
// K0: zero deg + cnt
// ---------------------------------------------------------------------------
__global__ void zero_kernel() {
    int i = blockIdx.x * blockDim.x + threadIdx.x;
    if (i < BN / 4) {
        reinterpret_cast<float4*>(g_deg)[i] = make_float4(0.f, 0.f, 0.f, 0.f);
        reinterpret_cast<int4*>(g_cnt)[i]   = make_int4(0, 0, 0, 0);
    }
}

// ---------------------------------------------------------------------------
// K1: histogram + degree in one pass over the edge list
// ---------------------------------------------------------------------------
__global__ void hist_kernel(const int* __restrict__ eb, const int* __restrict__ er,
                            const float* __restrict__ ev, int E) {
    int e = blockIdx.x * blockDim.x + threadIdx.x;
    if (e >= E) return;
    int dst = __ldg(eb + e) * NN + __ldg(er + e);
    atomicAdd(&g_cnt[dst], 1);
    atomicAdd(&g_deg[dst], fabsf(__ldg(ev + e)));
}

// ---------------------------------------------------------------------------
// K2: exclusive prefix sum over 64K counts — single block, 1024 threads
// ---------------------------------------------------------------------------
__global__ __launch_bounds__(1024) void scan_kernel() {
    const int t = threadIdx.x;
    const int lane = t & 31, wid = t >> 5;
    const int4* cnt4 = reinterpret_cast<const int4*>(g_cnt);

    int s = 0;
#pragma unroll
    for (int i = 0; i < 16; i++) {
        int4 c = cnt4[t * 16 + i];
        s += c.x + c.y + c.z + c.w;
    }
    int v = s;
#pragma unroll
    for (int o = 1; o < 32; o <<= 1) {
        int n = __shfl_up_sync(0xffffffffu, v, o);
        if (lane >= o) v += n;
    }
    __shared__ int wsum[32];
    if (lane == 31) wsum[wid] = v;
    __syncthreads();
    if (wid == 0) {
        int w = wsum[lane];
#pragma unroll
        for (int o = 1; o < 32; o <<= 1) {
            int n = __shfl_up_sync(0xffffffffu, w, o);
            if (lane >= o) w += n;
        }
        wsum[lane] = w;
    }
    __syncthreads();
    int run = v - s + (wid ? wsum[wid - 1] : 0);

#pragma unroll
    for (int i = 0; i < 16; i++) {
        int4 c = cnt4[t * 16 + i];
        int b = t * 64 + i * 4;
        g_rowptr[b + 0] = run; g_cur[b + 0] = run; run += c.x;
        g_rowptr[b + 1] = run; g_cur[b + 1] = run; run += c.y;
        g_rowptr[b + 2] = run; g_cur[b + 2] = run; run += c.z;
        g_rowptr[b + 3] = run; g_cur[b + 3] = run; run += c.w;
    }
    if (t == 1023) g_rowptr[BN] = run;
}

// ---------------------------------------------------------------------------
// K3: scatter edges into destination-sorted order, packed (val | src) 8B
// ---------------------------------------------------------------------------
__global__ void scatter_kernel(const int* __restrict__ eb, const int* __restrict__ er,
                               const int* __restrict__ ec, const float* __restrict__ ev,
                               int E) {
    int e = blockIdx.x * blockDim.x + threadIdx.x;
    if (e >= E) return;
    int b   = __ldg(eb + e);
    int dst = b * NN + __ldg(er + e);
    int src = b * NN + __ldg(ec + e);
    unsigned int vb = __float_as_uint(__ldg(ev + e));
    int pos = atomicAdd(&g_cur[dst], 1);
    g_sorted[pos] = ((unsigned long long)vb << 32) | (unsigned int)src;
}

// ---------------------------------------------------------------------------
// K4: y = (x @ W) * rsqrt(deg + 1e-6)   — fp32x2 packed-FMA GEMM
// ---------------------------------------------------------------------------
__global__ __launch_bounds__(256) void gemm_kernel(const float* __restrict__ x,
                                                   const float* __restrict__ Wg) {
    __shared__ float2 Xs[64][32];     // 16 KB, duplicated x values
    __shared__ float  Ws[32][128];    // 16 KB
    __shared__ float  snorm[64];

    const int tid = threadIdx.x;
    const int rowBase = blockIdx.x * 64;
    if (tid < 64) snorm[tid] = rsqrtf(g_deg[rowBase + tid] + 1e-6f);

    const int tx = tid & 31;
    const int ty = tid >> 5;
    const int c0 = tx * 2;

    unsigned long long accA[8], accB[8];
#pragma unroll
    for (int i = 0; i < 8; i++) { accA[i] = 0ULL; accB[i] = 0ULL; }

    for (int kc = 0; kc < 4; kc++) {
        for (int t = tid; t < 512; t += 256) {
            int r = t >> 3, q = t & 7;
            float4 xv = *reinterpret_cast<const float4*>(
                x + (size_t)(rowBase + r) * DD + kc * 32 + q * 4);
            int cc = q * 4;
            Xs[r][cc + 0] = make_float2(xv.x, xv.x);
            Xs[r][cc + 1] = make_float2(xv.y, xv.y);
            Xs[r][cc + 2] = make_float2(xv.z, xv.z);
            Xs[r][cc + 3] = make_float2(xv.w, xv.w);
        }
        for (int t = tid; t < 1024; t += 256) {
            int kk = t >> 5, q = t & 31;
            *reinterpret_cast<float4*>(&Ws[kk][q * 4]) =
                *reinterpret_cast<const float4*>(Wg + (size_t)(kc * 32 + kk) * DD + q * 4);
        }
        __syncthreads();

#pragma unroll
        for (int kk = 0; kk < 32; kk++) {
            unsigned long long wA = *reinterpret_cast<const unsigned long long*>(&Ws[kk][c0]);
            unsigned long long wB = *reinterpret_cast<const unsigned long long*>(&Ws[kk][c0 + 64]);
#pragma unroll
            for (int i = 0; i < 8; i++) {
                unsigned long long xa =
                    *reinterpret_cast<const unsigned long long*>(&Xs[ty + i * 8][kk]);
                FMA2(accA[i], xa, wA);
                FMA2(accB[i], xa, wB);
            }
        }
        __syncthreads();
    }

#pragma unroll
    for (int i = 0; i < 8; i++) {
        int r = ty + i * 8;
        float n = snorm[r];
        float2 a = *reinterpret_cast<float2*>(&accA[i]);
        float2 b2 = *reinterpret_cast<float2*>(&accB[i]);
        float* yo = g_y + (size_t)(rowBase + r) * DD;
        *reinterpret_cast<float2*>(&yo[c0])      = make_float2(a.x * n, a.y * n);
        *reinterpret_cast<float2*>(&yo[c0 + 64]) = make_float2(b2.x * n, b2.y * n);
    }
}

// ---------------------------------------------------------------------------
// K5: gather — one warp per destination row, 8-deep batched loads (MLP=8).
//     Register accumulation; fused norm+bias+relu and a single STG.128.
// ---------------------------------------------------------------------------
__global__ __launch_bounds__(256) void gather_kernel(const float* __restrict__ bias,
                                                     float* __restrict__ out) {
    int row = (blockIdx.x * blockDim.x + threadIdx.x) >> 5;
    if (row >= BN) return;
    const int lane = threadIdx.x & 31;

    const int start = __ldg(&g_rowptr[row]);
    const int end   = __ldg(&g_rowptr[row + 1]);
    const float4* __restrict__ ybase =
        reinterpret_cast<const float4*>(g_y) + lane;        // + s*32 per row

    float4 acc = make_float4(0.f, 0.f, 0.f, 0.f);
    int e = start;

    // 8-wide batches: 8 independent 8B edge loads, then 8 independent LDG.128
    while (e + 8 <= end) {
        unsigned long long p[8];
#pragma unroll
        for (int j = 0; j < 8; j++) p[j] = g_sorted[e + j];
        float4 y[8];
#pragma unroll
        for (int j = 0; j < 8; j++) {
            int s = (int)(unsigned int)p[j];
            y[j] = ybase[(size_t)s * 32];
        }
#pragma unroll
        for (int j = 0; j < 8; j++) {
            float v = __uint_as_float((unsigned int)(p[j] >> 32));
            acc.x = fmaf(v, y[j].x, acc.x); acc.y = fmaf(v, y[j].y, acc.y);
            acc.z = fmaf(v, y[j].z, acc.z); acc.w = fmaf(v, y[j].w, acc.w);
        }
        e += 8;
    }
    // 2-wide tail
    while (e + 2 <= end) {
        unsigned long long p0 = g_sorted[e];
        unsigned long long p1 = g_sorted[e + 1];
        float4 y0 = ybase[(size_t)(unsigned int)(p0 & 0xffffffffu) * 32];
        float4 y1 = ybase[(size_t)(unsigned int)(p1 & 0xffffffffu) * 32];
        float v0 = __uint_as_float((unsigned int)(p0 >> 32));
        float v1 = __uint_as_float((unsigned int)(p1 >> 32));
        acc.x = fmaf(v0, y0.x, acc.x); acc.y = fmaf(v0, y0.y, acc.y);
        acc.z = fmaf(v0, y0.z, acc.z); acc.w = fmaf(v0, y0.w, acc.w);
        acc.x = fmaf(v1, y1.x, acc.x); acc.y = fmaf(v1, y1.y, acc.y);
        acc.z = fmaf(v1, y1.z, acc.z); acc.w = fmaf(v1, y1.w, acc.w);
        e += 2;
    }
    if (e < end) {
        unsigned long long p0 = g_sorted[e];
        float4 y0 = ybase[(size_t)(unsigned int)(p0 & 0xffffffffu) * 32];
        float v0 = __uint_as_float((unsigned int)(p0 >> 32));
        acc.x = fmaf(v0, y0.x, acc.x); acc.y = fmaf(v0, y0.y, acc.y);
        acc.z = fmaf(v0, y0.z, acc.z); acc.w = fmaf(v0, y0.w, acc.w);
    }

    float nrm = rsqrtf(__ldg(&g_deg[row]) + 1e-6f);
    float4 bv = *reinterpret_cast<const float4*>(bias + lane * 4);
    acc.x = fmaxf(fmaf(acc.x, nrm, bv.x), 0.f);
    acc.y = fmaxf(fmaf(acc.y, nrm, bv.y), 0.f);
    acc.z = fmaxf(fmaf(acc.z, nrm, bv.z), 0.f);
    acc.w = fmaxf(fmaf(acc.w, nrm, bv.w), 0.f);
    *reinterpret_cast<float4*>(out + (size_t)row * DD + lane * 4) = acc;
}

// ---------------------------------------------------------------------------
// launch — inputs per metadata order:
// x, W, b, edge_b, edge_row, edge_col, edge_vals, k(unused)
// ---------------------------------------------------------------------------
extern "C" void kernel_launch(void* const* d_in, const int* in_sizes, int n_in,
                              void* d_out, int out_size) {
    const float* x    = (const float*)d_in[0];
    const float* Wg   = (const float*)d_in[1];
    const float* bias = (const float*)d_in[2];
    const int*   eb   = (const int*)d_in[3];
    const int*   er   = (const int*)d_in[4];
    const int*   ec   = (const int*)d_in[5];
    const float* ev   = (const float*)d_in[6];
    const int E = in_sizes[3];
    float* out = (float*)d_out;

    zero_kernel<<<(BN / 4 + 255) / 256, 256>>>();
    hist_kernel<<<(E + 255) / 256, 256>>>(eb, er, ev, E);
    scan_kernel<<<1, 1024>>>();
    scatter_kernel<<<(E + 255) / 256, 256>>>(eb, er, ec, ev, E);
    gemm_kernel<<<BN / 64, 256>>>(x, Wg);
    gather_kernel<<<(BN * 32) / 256, 256>>>(bias, out);
}

// round 7
// speedup vs baseline: 1.0823x; 1.0823x over previous
#include <cuda_runtime.h>
#include <cuda_fp16.h>

// Fixed problem shape (SGConv_52613349376206): B=4, N=16384, D=128, E=1048576
#define BB 4
#define NN 16384
#define DD 128
#define BN (BB * NN)   // 65536 rows
#define GEMM_BLOCKS (BN / 64)   // 1024

// Scratch (static __device__ arrays; BSS-zeroed at load, re-zeroed by gather tail)
__device__ float              g_deg[BN];                 // 256 KB  sum |val| per dst
__device__ int                g_cnt[BN];                 // 256 KB  edge count per dst
__device__ int                g_rowptr[BN + 1];          // CSR row pointers
__device__ int                g_cur[BN];                 // scatter cursors
__device__ unsigned long long g_sorted[1 << 20];         // 8 MB   packed (val,src)
__device__ __half             g_yh[(size_t)BN * DD];     // 16 MB  y in fp16

// packed fp32x2 FMA (Blackwell)
#define FMA2(acc, a, b) \
    asm("fma.rn.f32x2 %0, %1, %2, %0;" : "+l"(acc) : "l"(a), "l"(b))

// ---------------------------------------------------------------------------
// K1: histogram + degree in one pass (deg/cnt pre-zeroed by previous call)
// ---------------------------------------------------------------------------
__global__ void hist_kernel(const int* __restrict__ eb, const int* __restrict__ er,
                            const float* __restrict__ ev, int E) {
    int e = blockIdx.x * blockDim.x + threadIdx.x;
    if (e >= E) return;
    int dst = __ldg(eb + e) * NN + __ldg(er + e);
    atomicAdd(&g_cnt[dst], 1);
    atomicAdd(&g_deg[dst], fabsf(__ldg(ev + e)));
}

// ---------------------------------------------------------------------------
// K2: exclusive prefix sum over 64K counts — single block, 1024 threads
// ---------------------------------------------------------------------------
__global__ __launch_bounds__(1024) void scan_kernel() {
    const int t = threadIdx.x;
    const int lane = t & 31, wid = t >> 5;
    const int4* cnt4 = reinterpret_cast<const int4*>(g_cnt);

    int s = 0;
#pragma unroll
    for (int i = 0; i < 16; i++) {
        int4 c = cnt4[t * 16 + i];
        s += c.x + c.y + c.z + c.w;
    }
    int v = s;
#pragma unroll
    for (int o = 1; o < 32; o <<= 1) {
        int n = __shfl_up_sync(0xffffffffu, v, o);
        if (lane >= o) v += n;
    }
    __shared__ int wsum[32];
    if (lane == 31) wsum[wid] = v;
    __syncthreads();
    if (wid == 0) {
        int w = wsum[lane];
#pragma unroll
        for (int o = 1; o < 32; o <<= 1) {
            int n = __shfl_up_sync(0xffffffffu, w, o);
            if (lane >= o) w += n;
        }
        wsum[lane] = w;
    }
    __syncthreads();
    int run = v - s + (wid ? wsum[wid - 1] : 0);

#pragma unroll
    for (int i = 0; i < 16; i++) {
        int4 c = cnt4[t * 16 + i];
        int b = t * 64 + i * 4;
        g_rowptr[b + 0] = run; g_cur[b + 0] = run; run += c.x;
        g_rowptr[b + 1] = run; g_cur[b + 1] = run; run += c.y;
        g_rowptr[b + 2] = run; g_cur[b + 2] = run; run += c.z;
        g_rowptr[b + 3] = run; g_cur[b + 3] = run; run += c.w;
    }
    if (t == 1023) g_rowptr[BN] = run;
}

// ---------------------------------------------------------------------------
// K3: FUSED gemm + scatter (independent work; scatter hides under gemm FMAs)
// blocks [0, GEMM_BLOCKS): y = fp16((x @ W) * rsqrt(deg+1e-6))
// blocks [GEMM_BLOCKS, ..): scatter edges into destination-sorted CSR order
// ---------------------------------------------------------------------------
__global__ __launch_bounds__(256) void gemm_scatter_kernel(
        const float* __restrict__ x, const float* __restrict__ Wg,
        const int* __restrict__ eb, const int* __restrict__ er,
        const int* __restrict__ ec, const float* __restrict__ ev, int E) {

    __shared__ float2 Xs[64][32];     // 16 KB, duplicated x values
    __shared__ float  Ws[32][128];    // 16 KB
    __shared__ float  snorm[64];

    if (blockIdx.x >= GEMM_BLOCKS) {
        // ---- scatter part ----
        int e = (blockIdx.x - GEMM_BLOCKS) * 256 + threadIdx.x;
        if (e < E) {
            int b   = __ldg(eb + e);
            int dst = b * NN + __ldg(er + e);
            int src = b * NN + __ldg(ec + e);
            unsigned int vb = __float_as_uint(__ldg(ev + e));
            int pos = atomicAdd(&g_cur[dst], 1);
            g_sorted[pos] = ((unsigned long long)vb << 32) | (unsigned int)src;
        }
        return;
    }

    // ---- gemm part ----
    const int tid = threadIdx.x;
    const int rowBase = blockIdx.x * 64;
    if (tid < 64) snorm[tid] = rsqrtf(g_deg[rowBase + tid] + 1e-6f);

    const int tx = tid & 31;
    const int ty = tid >> 5;
    const int c0 = tx * 2;

    unsigned long long accA[8], accB[8];
#pragma unroll
    for (int i = 0; i < 8; i++) { accA[i] = 0ULL; accB[i] = 0ULL; }

    for (int kc = 0; kc < 4; kc++) {
        for (int t = tid; t < 512; t += 256) {
            int r = t >> 3, q = t & 7;
            float4 xv = *reinterpret_cast<const float4*>(
                x + (size_t)(rowBase + r) * DD + kc * 32 + q * 4);
            int cc = q * 4;
            Xs[r][cc + 0] = make_float2(xv.x, xv.x);
            Xs[r][cc + 1] = make_float2(xv.y, xv.y);
            Xs[r][cc + 2] = make_float2(xv.z, xv.z);
            Xs[r][cc + 3] = make_float2(xv.w, xv.w);
        }
        for (int t = tid; t < 1024; t += 256) {
            int kk = t >> 5, q = t & 31;
            *reinterpret_cast<float4*>(&Ws[kk][q * 4]) =
                *reinterpret_cast<const float4*>(Wg + (size_t)(kc * 32 + kk) * DD + q * 4);
        }
        __syncthreads();

#pragma unroll
        for (int kk = 0; kk < 32; kk++) {
            unsigned long long wA = *reinterpret_cast<const unsigned long long*>(&Ws[kk][c0]);
            unsigned long long wB = *reinterpret_cast<const unsigned long long*>(&Ws[kk][c0 + 64]);
#pragma unroll
            for (int i = 0; i < 8; i++) {
                unsigned long long xa =
                    *reinterpret_cast<const unsigned long long*>(&Xs[ty + i * 8][kk]);
                FMA2(accA[i], xa, wA);
                FMA2(accB[i], xa, wB);
            }
        }
        __syncthreads();
    }

#pragma unroll
    for (int i = 0; i < 8; i++) {
        int r = ty + i * 8;
        float n = snorm[r];
        float2 a  = *reinterpret_cast<float2*>(&accA[i]);
        float2 b2 = *reinterpret_cast<float2*>(&accB[i]);
        __half* yo = g_yh + (size_t)(rowBase + r) * DD;
        *reinterpret_cast<__half2*>(yo + c0) =
            __float22half2_rn(make_float2(a.x * n, a.y * n));
        *reinterpret_cast<__half2*>(yo + c0 + 64) =
            __float22half2_rn(make_float2(b2.x * n, b2.y * n));
    }
}

// ---------------------------------------------------------------------------
// K4: gather — one warp per destination row. Masked 8-wide batches: one
//     coalesced LDG.64 fetches 8 packed edges (shfl-broadcast), then 8
//     independent fp16 y-row loads (2 lines each). fp32 accumulation; fused
//     norm+bias+relu + single STG.128. Tail: warp zeroes deg/cnt for its row
//     (state reset for the next call — graph-replay safe).
// ---------------------------------------------------------------------------
__global__ __launch_bounds__(256) void gather_kernel(const float* __restrict__ bias,
                                                     float* __restrict__ out) {
    int row = (blockIdx.x * blockDim.x + threadIdx.x) >> 5;
    if (row >= BN) return;
    const int lane = threadIdx.x & 31;

    const int start = __ldg(&g_rowptr[row]);
    const int end   = __ldg(&g_rowptr[row + 1]);
    const __half* __restrict__ yb = g_yh + (size_t)lane * 4;   // + src*DD per edge

    float4 acc = make_float4(0.f, 0.f, 0.f, 0.f);
    const int li = lane & 7;

    for (int base = start; base < end; base += 8) {
        const int rem = end - base;                  // >= 1
        // one coalesced 64B load of up to 8 packed edges (clamped -> valid addr)
        unsigned long long pl = g_sorted[base + (li < rem ? li : 0)];
        uint2  q[8];
        float  vv[8];
#pragma unroll
        for (int j = 0; j < 8; j++) {
            unsigned long long pj = __shfl_sync(0xffffffffu, pl, j);
            int s = (int)(unsigned int)pj;
            vv[j] = (j < rem) ? __uint_as_float((unsigned int)(pj >> 32)) : 0.f;
            q[j]  = *reinterpret_cast<const uint2*>(yb + (size_t)s * DD);
        }
#pragma unroll
        for (int j = 0; j < 8; j++) {
            float2 f0 = __half22float2(*reinterpret_cast<const __half2*>(&q[j].x));
            float2 f1 = __half22float2(*reinterpret_cast<const __half2*>(&q[j].y));
            acc.x = fmaf(vv[j], f0.x, acc.x);
            acc.y = fmaf(vv[j], f0.y, acc.y);
            acc.z = fmaf(vv[j], f1.x, acc.z);
            acc.w = fmaf(vv[j], f1.y, acc.w);
        }
    }

    float nrm = rsqrtf(__ldg(&g_deg[row]) + 1e-6f);
    float4 bv = *reinterpret_cast<const float4*>(bias + lane * 4);
    acc.x = fmaxf(fmaf(acc.x, nrm, bv.x), 0.f);
    acc.y = fmaxf(fmaf(acc.y, nrm, bv.y), 0.f);
    acc.z = fmaxf(fmaf(acc.z, nrm, bv.z), 0.f);
    acc.w = fmaxf(fmaf(acc.w, nrm, bv.w), 0.f);
    *reinterpret_cast<float4*>(out + (size_t)row * DD + lane * 4) = acc;

    // reset scratch for the next call (row-owned: race-free)
    if (lane == 0) { g_deg[row] = 0.f; g_cnt[row] = 0; }
}

// ---------------------------------------------------------------------------
// launch — inputs per metadata order:
// x, W, b, edge_b, edge_row, edge_col, edge_vals, k(unused)
// ---------------------------------------------------------------------------
extern "C" void kernel_launch(void* const* d_in, const int* in_sizes, int n_in,
                              void* d_out, int out_size) {
    const float* x    = (const float*)d_in[0];
    const float* Wg   = (const float*)d_in[1];
    const float* bias = (const float*)d_in[2];
    const int*   eb   = (const int*)d_in[3];
    const int*   er   = (const int*)d_in[4];
    const int*   ec   = (const int*)d_in[5];
    const float* ev   = (const float*)d_in[6];
    const int E = in_sizes[3];
    float* out = (float*)d_out;

    hist_kernel<<<(E + 255) / 256, 256>>>(eb, er, ev, E);
    scan_kernel<<<1, 1024>>>();
    gemm_scatter_kernel<<<GEMM_BLOCKS + (E + 255) / 256, 256>>>(x, Wg, eb, er, ec, ev, E);
    gather_kernel<<<(BN * 32) / 256, 256>>>(bias, out);
}